// round 15
// baseline (speedup 1.0000x reference)
#include <cuda_runtime.h>
#include <cuda_bf16.h>
#include <cstdint>

// ---------------------------------------------------------------------------
// SSA attention, 3xTF32 pipeline, v15.
//  v15 = v14 with qkv_gemm rebuilt at 512 threads (16 warps, 32x32 per warp,
//  same 128x128 tile): regs/warp halved -> 2x warps resident -> latency
//  hiding. ncu r14 showed qkv at 177us, 1 CTA/SM (132 regs), issue 25%.
// ---------------------------------------------------------------------------

#define T_TOK   1024
#define NB      64
#define NEGBIG  (-1e30f)

__device__ float g_Weff[4096 * 512];
__device__ float2 g_cs[1024 * 32];      // (cos, sin) per (token, freq)
__device__ float g_kraw[T_TOK * 512];
__device__ float g_vraw[T_TOK * 512];
__device__ float g_Q[64 * T_TOK * 64];
__device__ float g_K[64 * T_TOK * 64];
__device__ float g_qm[64 * 64 * 64];
__device__ float g_km[64 * 64 * 64];
__device__ float g_ctx[T_TOK * 4096];
__device__ float g_part[4 * T_TOK * 512];
__device__ unsigned long long g_mask[64 * NB];

__device__ __forceinline__ float tf32r(float x) {
    uint32_t u;
    asm("cvt.rna.tf32.f32 %0, %1;" : "=r"(u) : "f"(x));
    return __uint_as_float(u);
}

__device__ __forceinline__ void mma8(float* c, const uint32_t* a, const uint32_t* b) {
    asm volatile(
        "mma.sync.aligned.m16n8k8.row.col.f32.tf32.tf32.f32 "
        "{%0,%1,%2,%3}, {%4,%5,%6,%7}, {%8,%9}, {%0,%1,%2,%3};"
        : "+f"(c[0]), "+f"(c[1]), "+f"(c[2]), "+f"(c[3])
        : "r"(a[0]), "r"(a[1]), "r"(a[2]), "r"(a[3]), "r"(b[0]), "r"(b[1]));
}

// ---------------------------------------------------------------------------
__global__ void prep_cs()
{
    int idx = blockIdx.x * 256 + threadIdx.x;   // 32768 entries
    int f = idx & 31;
    int t = idx >> 5;
    float iv = (float)exp(-9.210340371976184 * (double)f / 32.0);
    float sn, cs;
    sincosf((float)t * iv, &sn, &cs);
    g_cs[idx] = make_float2(cs, sn);
}

// ---------------------------------------------------------------------------
// Q weight folding, 3xTF32 (validated r5-r14). Launched twice (cgbase 0/4).
// ---------------------------------------------------------------------------
__global__ __launch_bounds__(128)
void prep_fold(const float* __restrict__ A, const float* __restrict__ idb,
               const float* __restrict__ WQ, float* __restrict__ Weff, int cgbase)
{
    int h = blockIdx.x, cg = cgbase + blockIdx.y;
    int tid = threadIdx.x;
    int warp = tid >> 5, lane = tid & 31;
    int g = lane >> 2, tg = lane & 3;
    __shared__ float Th[64][64], Tl[64][64];
    __shared__ float Wh[64][32], Wl[64][32];

    for (int idx = tid; idx < 4096; idx += 128) {
        int e = idx >> 6, d = idx & 63;
        float v = A[d * 64 + e] - A[e * 64 + d];
        if (d == e) v += 1.f + idb[h * 64 + e];
        float hi = tf32r(v);
        Th[e][d] = hi;
        Tl[e][d] = tf32r(v - hi);
    }
    const float* Wsrc = WQ + (size_t)(h * 64) * 512;
    float* Wdst = Weff + (size_t)(h * 64) * 512;

    for (int chunk = cg * 2; chunk < cg * 2 + 2; ++chunk) {
        __syncthreads();
        for (int idx = tid; idx < 2048; idx += 128) {
            int d = idx >> 5, n = idx & 31;
            float v = Wsrc[(size_t)d * 512 + chunk * 32 + n];
            float hi = tf32r(v);
            Wh[d][n] = hi;
            Wl[d][n] = tf32r(v - hi);
        }
        __syncthreads();

        float c[4][4];
#pragma unroll
        for (int mt = 0; mt < 4; ++mt)
#pragma unroll
            for (int r = 0; r < 4; ++r) c[mt][r] = 0.f;

#pragma unroll
        for (int k0 = 0; k0 < 64; k0 += 8) {
            uint32_t ah[4][4], al[4][4], bh[2], bl[2];
#pragma unroll
            for (int mt = 0; mt < 4; ++mt) {
                int mb = mt * 16;
                ah[mt][0] = __float_as_uint(Th[mb + g][k0 + tg]);
                ah[mt][1] = __float_as_uint(Th[mb + g + 8][k0 + tg]);
                ah[mt][2] = __float_as_uint(Th[mb + g][k0 + tg + 4]);
                ah[mt][3] = __float_as_uint(Th[mb + g + 8][k0 + tg + 4]);
                al[mt][0] = __float_as_uint(Tl[mb + g][k0 + tg]);
                al[mt][1] = __float_as_uint(Tl[mb + g + 8][k0 + tg]);
                al[mt][2] = __float_as_uint(Tl[mb + g][k0 + tg + 4]);
                al[mt][3] = __float_as_uint(Tl[mb + g + 8][k0 + tg + 4]);
            }
            int nb = warp * 8;
            bh[0] = __float_as_uint(Wh[k0 + tg][nb + g]);
            bh[1] = __float_as_uint(Wh[k0 + tg + 4][nb + g]);
            bl[0] = __float_as_uint(Wl[k0 + tg][nb + g]);
            bl[1] = __float_as_uint(Wl[k0 + tg + 4][nb + g]);
#pragma unroll
            for (int mt = 0; mt < 4; ++mt) {
                mma8(c[mt], ah[mt], bh);
                mma8(c[mt], ah[mt], bl);
                mma8(c[mt], al[mt], bh);
            }
        }
#pragma unroll
        for (int mt = 0; mt < 4; ++mt) {
            int row = mt * 16 + g;
            int col = chunk * 32 + warp * 8 + 2 * tg;
            *reinterpret_cast<float2*>(Wdst + (size_t)row * 512 + col)
                = make_float2(c[mt][0], c[mt][1]);
            *reinterpret_cast<float2*>(Wdst + (size_t)(row + 8) * 512 + col)
                = make_float2(c[mt][2], c[mt][3]);
        }
    }
}

// ---------------------------------------------------------------------------
// QKV projection, 3xTF32, v15: 512 threads, 16 warps (4x4), 32x32 per warp.
// Same 128x128 tile, same k-order -> bit-identical results.
// ---------------------------------------------------------------------------
__global__ __launch_bounds__(512)
void qkv_gemm(const float* __restrict__ Ag, const float* __restrict__ Weff,
              const float* __restrict__ WKw, const float* __restrict__ WVw,
              const float* __restrict__ bK, const float* __restrict__ bV,
              float* __restrict__ Qo, float* __restrict__ kraw, float* __restrict__ vraw)
{
    const int K = 512;
    __shared__ float Ah[16][132], Bh[16][132];
    __shared__ float Al[16][132], Bl[16][132];
    int tid = threadIdx.x;
    int warp = tid >> 5, lane = tid & 31;
    int wm = warp >> 2, wn = warp & 3;
    int g = lane >> 2, tg = lane & 3;
    int m0 = blockIdx.y * 128, n0 = blockIdx.x * 128;

    const float* Bsrc;
    int nbase;
    if (n0 < 4096)      { Bsrc = Weff; nbase = n0; }
    else if (n0 < 4608) { Bsrc = WKw;  nbase = n0 - 4096; }
    else                { Bsrc = WVw;  nbase = n0 - 4608; }

    int rowA = tid >> 2;
    int kqA  = (tid & 3) << 2;

    float c[2][4][4];
#pragma unroll
    for (int i = 0; i < 2; ++i)
#pragma unroll
        for (int j = 0; j < 4; ++j)
#pragma unroll
            for (int r = 0; r < 4; ++r) c[i][j][r] = 0.f;

    float4 pa, pb;
    pa = *reinterpret_cast<const float4*>(Ag + (size_t)(m0 + rowA) * K + kqA);
    pb = *reinterpret_cast<const float4*>(Bsrc + (size_t)(nbase + rowA) * K + kqA);

    for (int k0 = 0; k0 < K; k0 += 16) {
        {
            float4 a = pa;
            float h0 = tf32r(a.x), h1 = tf32r(a.y), h2 = tf32r(a.z), h3 = tf32r(a.w);
            Ah[kqA + 0][rowA] = h0; Ah[kqA + 1][rowA] = h1;
            Ah[kqA + 2][rowA] = h2; Ah[kqA + 3][rowA] = h3;
            Al[kqA + 0][rowA] = tf32r(a.x - h0); Al[kqA + 1][rowA] = tf32r(a.y - h1);
            Al[kqA + 2][rowA] = tf32r(a.z - h2); Al[kqA + 3][rowA] = tf32r(a.w - h3);
            float4 b = pb;
            float i0 = tf32r(b.x), i1 = tf32r(b.y), i2 = tf32r(b.z), i3 = tf32r(b.w);
            Bh[kqA + 0][rowA] = i0; Bh[kqA + 1][rowA] = i1;
            Bh[kqA + 2][rowA] = i2; Bh[kqA + 3][rowA] = i3;
            Bl[kqA + 0][rowA] = tf32r(b.x - i0); Bl[kqA + 1][rowA] = tf32r(b.y - i1);
            Bl[kqA + 2][rowA] = tf32r(b.z - i2); Bl[kqA + 3][rowA] = tf32r(b.w - i3);
        }
        __syncthreads();

        if (k0 + 16 < K) {
            pa = *reinterpret_cast<const float4*>(
                Ag + (size_t)(m0 + rowA) * K + k0 + 16 + kqA);
            pb = *reinterpret_cast<const float4*>(
                Bsrc + (size_t)(nbase + rowA) * K + k0 + 16 + kqA);
        }

#pragma unroll
        for (int h8 = 0; h8 < 16; h8 += 8) {
            uint32_t afh[2][4], bfh[4][2];
            uint32_t afl[2][4], bfl[4][2];
#pragma unroll
            for (int mt = 0; mt < 2; ++mt) {
                int mb = wm * 32 + mt * 16;
                afh[mt][0] = __float_as_uint(Ah[h8 + tg][mb + g]);
                afh[mt][1] = __float_as_uint(Ah[h8 + tg][mb + g + 8]);
                afh[mt][2] = __float_as_uint(Ah[h8 + tg + 4][mb + g]);
                afh[mt][3] = __float_as_uint(Ah[h8 + tg + 4][mb + g + 8]);
                afl[mt][0] = __float_as_uint(Al[h8 + tg][mb + g]);
                afl[mt][1] = __float_as_uint(Al[h8 + tg][mb + g + 8]);
                afl[mt][2] = __float_as_uint(Al[h8 + tg + 4][mb + g]);
                afl[mt][3] = __float_as_uint(Al[h8 + tg + 4][mb + g + 8]);
            }
#pragma unroll
            for (int nt = 0; nt < 4; ++nt) {
                int nb = wn * 32 + nt * 8;
                bfh[nt][0] = __float_as_uint(Bh[h8 + tg][nb + g]);
                bfh[nt][1] = __float_as_uint(Bh[h8 + tg + 4][nb + g]);
                bfl[nt][0] = __float_as_uint(Bl[h8 + tg][nb + g]);
                bfl[nt][1] = __float_as_uint(Bl[h8 + tg + 4][nb + g]);
            }
#pragma unroll
            for (int mt = 0; mt < 2; ++mt)
#pragma unroll
                for (int nt = 0; nt < 4; ++nt) {
                    mma8(c[mt][nt], afh[mt], bfh[nt]);
                    mma8(c[mt][nt], afh[mt], bfl[nt]);
                    mma8(c[mt][nt], afl[mt], bfh[nt]);
                }
        }
        __syncthreads();
    }

#pragma unroll
    for (int mt = 0; mt < 2; ++mt) {
        int row = m0 + wm * 32 + mt * 16 + g;
#pragma unroll
        for (int nt = 0; nt < 4; ++nt) {
            int col = n0 + wn * 32 + nt * 8 + 2 * tg;
            float c0 = c[mt][nt][0], c1 = c[mt][nt][1];
            float c2 = c[mt][nt][2], c3 = c[mt][nt][3];
            if (n0 < 4096) {
                int h = col >> 6, f = (col & 63) >> 1;
                float2 cs0 = g_cs[row * 32 + f];
                float2 cs1 = g_cs[(row + 8) * 32 + f];
                float* q0 = Qo + ((size_t)h * T_TOK + row) * 64;
                float* q1 = Qo + ((size_t)h * T_TOK + row + 8) * 64;
                q0[f]      = c0 * cs0.x - c1 * cs0.y;
                q0[f + 32] = c0 * cs0.y + c1 * cs0.x;
                q1[f]      = c2 * cs1.x - c3 * cs1.y;
                q1[f + 32] = c2 * cs1.y + c3 * cs1.x;
            } else if (n0 < 4608) {
                int cc = col - 4096;
                float b0 = bK[cc], b1 = bK[cc + 1];
                *reinterpret_cast<float2*>(kraw + (size_t)row * 512 + cc)
                    = make_float2(c0 + b0, c1 + b1);
                *reinterpret_cast<float2*>(kraw + (size_t)(row + 8) * 512 + cc)
                    = make_float2(c2 + b0, c3 + b1);
            } else {
                int cc = col - 4608;
                float b0 = bV[cc], b1 = bV[cc + 1];
                *reinterpret_cast<float2*>(vraw + (size_t)row * 512 + cc)
                    = make_float2(c0 + b0, c1 + b1);
                *reinterpret_cast<float2*>(vraw + (size_t)(row + 8) * 512 + cc)
                    = make_float2(c2 + b0, c3 + b1);
            }
        }
    }
}

// ---------------------------------------------------------------------------
// Fused K transform (validated r13/r14), rope tail reads g_cs LUT.
// ---------------------------------------------------------------------------
__global__ __launch_bounds__(256)
void km_krope(const float* __restrict__ A, const float* __restrict__ idb,
              const float* __restrict__ kraw, float* __restrict__ Ko)
{
    int rt = blockIdx.x, s = blockIdx.y;
    int tid = threadIdx.x;
    int warp = tid >> 5, lane = tid & 31;
    int g = lane >> 2, tg = lane & 3;
    __shared__ float Mh[64][64], Ml[64][64];

    for (int idx = tid; idx < 4096; idx += 256) {
        int d = idx >> 6, e = idx & 63;
        float v = A[d * 64 + e] - A[e * 64 + d];
        float hi = tf32r(v);
        Mh[d][e] = hi;
        Ml[d][e] = tf32r(v - hi);
    }
    __syncthreads();

    int t0 = rt * 128 + warp * 16;
    const float* Ap = kraw + (size_t)t0 * 512 + s * 64;

    float c[8][4];
#pragma unroll
    for (int nt = 0; nt < 8; ++nt)
#pragma unroll
        for (int r = 0; r < 4; ++r) c[nt][r] = 0.f;

#pragma unroll
    for (int k0 = 0; k0 < 64; k0 += 8) {
        float a0 = Ap[(size_t)g * 512 + k0 + tg];
        float a1 = Ap[(size_t)(g + 8) * 512 + k0 + tg];
        float a2 = Ap[(size_t)g * 512 + k0 + tg + 4];
        float a3 = Ap[(size_t)(g + 8) * 512 + k0 + tg + 4];
        uint32_t ah[4], al[4];
        float h0 = tf32r(a0), h1 = tf32r(a1), h2 = tf32r(a2), h3 = tf32r(a3);
        ah[0] = __float_as_uint(h0); al[0] = __float_as_uint(tf32r(a0 - h0));
        ah[1] = __float_as_uint(h1); al[1] = __float_as_uint(tf32r(a1 - h1));
        ah[2] = __float_as_uint(h2); al[2] = __float_as_uint(tf32r(a2 - h2));
        ah[3] = __float_as_uint(h3); al[3] = __float_as_uint(tf32r(a3 - h3));
#pragma unroll
        for (int nt = 0; nt < 8; ++nt) {
            uint32_t bh[2], bl[2];
            int nb = nt * 8;
            bh[0] = __float_as_uint(Mh[k0 + tg][nb + g]);
            bh[1] = __float_as_uint(Mh[k0 + tg + 4][nb + g]);
            bl[0] = __float_as_uint(Ml[k0 + tg][nb + g]);
            bl[1] = __float_as_uint(Ml[k0 + tg + 4][nb + g]);
            mma8(c[nt], ah, bh);
            mma8(c[nt], ah, bl);
            mma8(c[nt], al, bh);
        }
    }

    int ta = t0 + g, tb = ta + 8;
    float snA[8], csA[8], snB[8], csB[8];
    float kA0[8], kA1[8], kB0[8], kB1[8];
#pragma unroll
    for (int nt = 0; nt < 8; ++nt) {
        int f = nt * 4 + tg;
        float2 cA = g_cs[ta * 32 + f];
        float2 cB = g_cs[tb * 32 + f];
        csA[nt] = cA.x; snA[nt] = cA.y;
        csB[nt] = cB.x; snB[nt] = cB.y;
        int col = nt * 8 + 2 * tg;
        kA0[nt] = kraw[(size_t)ta * 512 + s * 64 + col];
        kA1[nt] = kraw[(size_t)ta * 512 + s * 64 + col + 1];
        kB0[nt] = kraw[(size_t)tb * 512 + s * 64 + col];
        kB1[nt] = kraw[(size_t)tb * 512 + s * 64 + col + 1];
    }

#pragma unroll
    for (int hh = 0; hh < 8; ++hh) {
        int h = hh * 8 + s;
        float* koA = Ko + ((size_t)h * T_TOK + ta) * 64;
        float* koB = Ko + ((size_t)h * T_TOK + tb) * 64;
#pragma unroll
        for (int nt = 0; nt < 8; ++nt) {
            int col = nt * 8 + 2 * tg;
            int f = nt * 4 + tg;
            float ib0 = 1.f + idb[h * 64 + col];
            float ib1 = 1.f + idb[h * 64 + col + 1];
            float vA0 = c[nt][0] + kA0[nt] * ib0;
            float vA1 = c[nt][1] + kA1[nt] * ib1;
            float vB0 = c[nt][2] + kB0[nt] * ib0;
            float vB1 = c[nt][3] + kB1[nt] * ib1;
            koA[f]      = vA0 * csA[nt] - vA1 * snA[nt];
            koA[f + 32] = vA0 * snA[nt] + vA1 * csA[nt];
            koB[f]      = vB0 * csB[nt] - vB1 * snB[nt];
            koB[f + 32] = vB0 * snB[nt] + vB1 * csB[nt];
        }
    }
}

// ---------------------------------------------------------------------------
// Output projection, single tf32, split-K, register prefetch (validated).
// ---------------------------------------------------------------------------
template<int SPLITK>
__global__ __launch_bounds__(256)
void mma_gemm_nn(const float* __restrict__ Ag, const float* __restrict__ Bg,
                 float* __restrict__ Cg, int M, int N, int K)
{
    __shared__ float As[16][132];
    __shared__ float Bs[16][132];
    int tid = threadIdx.x;
    int warp = tid >> 5, lane = tid & 31;
    int wm = warp >> 2, wn = warp & 3;
    int g = lane >> 2, tg = lane & 3;
    int m0 = blockIdx.y * 128, n0 = blockIdx.x * 128;
    int kchunk = K / SPLITK;
    int kbeg = blockIdx.z * kchunk;
    int kend = kbeg + kchunk;

    int rowA[2], kqA[2], rB[2], cB[2];
#pragma unroll
    for (int q = 0; q < 2; ++q) {
        int idx = q * 256 + tid;
        rowA[q] = idx >> 2; kqA[q] = (idx & 3) << 2;
        rB[q] = idx >> 5;   cB[q]  = (idx & 31) << 2;
    }

    float c[4][4][4];
#pragma unroll
    for (int i = 0; i < 4; ++i)
#pragma unroll
        for (int j = 0; j < 4; ++j)
#pragma unroll
            for (int r = 0; r < 4; ++r) c[i][j][r] = 0.f;

    float4 pa[2], pb[2];
#pragma unroll
    for (int q = 0; q < 2; ++q) {
        pa[q] = *reinterpret_cast<const float4*>(Ag + (size_t)(m0 + rowA[q]) * K + kbeg + kqA[q]);
        pb[q] = *reinterpret_cast<const float4*>(Bg + (size_t)(kbeg + rB[q]) * N + n0 + cB[q]);
    }

    for (int k0 = kbeg; k0 < kend; k0 += 16) {
#pragma unroll
        for (int q = 0; q < 2; ++q) {
            int row = rowA[q], kq = kqA[q];
            float4 a = pa[q];
            As[kq + 0][row] = tf32r(a.x); As[kq + 1][row] = tf32r(a.y);
            As[kq + 2][row] = tf32r(a.z); As[kq + 3][row] = tf32r(a.w);
            float4 b = pb[q];
            Bs[rB[q]][cB[q] + 0] = tf32r(b.x); Bs[rB[q]][cB[q] + 1] = tf32r(b.y);
            Bs[rB[q]][cB[q] + 2] = tf32r(b.z); Bs[rB[q]][cB[q] + 3] = tf32r(b.w);
        }
        __syncthreads();

        if (k0 + 16 < kend) {
#pragma unroll
            for (int q = 0; q < 2; ++q) {
                pa[q] = *reinterpret_cast<const float4*>(
                    Ag + (size_t)(m0 + rowA[q]) * K + k0 + 16 + kqA[q]);
                pb[q] = *reinterpret_cast<const float4*>(
                    Bg + (size_t)(k0 + 16 + rB[q]) * N + n0 + cB[q]);
            }
        }

#pragma unroll
        for (int h8 = 0; h8 < 16; h8 += 8) {
            uint32_t af[4][4], bf[4][2];
#pragma unroll
            for (int mt = 0; mt < 4; ++mt) {
                int mb = wm * 64 + mt * 16;
                af[mt][0] = __float_as_uint(As[h8 + tg][mb + g]);
                af[mt][1] = __float_as_uint(As[h8 + tg][mb + g + 8]);
                af[mt][2] = __float_as_uint(As[h8 + tg + 4][mb + g]);
                af[mt][3] = __float_as_uint(As[h8 + tg + 4][mb + g + 8]);
            }
#pragma unroll
            for (int nt = 0; nt < 4; ++nt) {
                int nb = wn * 32 + nt * 8;
                bf[nt][0] = __float_as_uint(Bs[h8 + tg][nb + g]);
                bf[nt][1] = __float_as_uint(Bs[h8 + tg + 4][nb + g]);
            }
#pragma unroll
            for (int mt = 0; mt < 4; ++mt)
#pragma unroll
                for (int nt = 0; nt < 4; ++nt) mma8(c[mt][nt], af[mt], bf[nt]);
        }
        __syncthreads();
    }

    float* Cp = Cg + (size_t)blockIdx.z * M * N;
#pragma unroll
    for (int mt = 0; mt < 4; ++mt) {
        int row = m0 + wm * 64 + mt * 16 + g;
#pragma unroll
        for (int nt = 0; nt < 4; ++nt) {
            int col = n0 + wn * 32 + nt * 8 + 2 * tg;
            *reinterpret_cast<float2*>(Cp + (size_t)row * N + col)
                = make_float2(c[mt][nt][0], c[mt][nt][1]);
            *reinterpret_cast<float2*>(Cp + (size_t)(row + 8) * N + col)
                = make_float2(c[mt][nt][2], c[mt][nt][3]);
        }
    }
}

// ---------------------------------------------------------------------------
// bmeans: 16-token block means of Q and K (validated r12-r14).
// ---------------------------------------------------------------------------
__global__ __launch_bounds__(256)
void bmeans_kernel(const float* __restrict__ Q, const float* __restrict__ K,
                   float* __restrict__ qm, float* __restrict__ km)
{
    int h = blockIdx.x, quarter = blockIdx.y;
    int tid = threadIdx.x;
    for (int it = 0; it < 4; ++it) {
        int idx = it * 256 + tid;
        int blk = quarter * 16 + (idx >> 6);
        int d = idx & 63;
        const float* Qp = Q + ((size_t)h * T_TOK + blk * 16) * 64 + d;
        const float* Kp = K + ((size_t)h * T_TOK + blk * 16) * 64 + d;
        float sq = 0.f, sk = 0.f;
#pragma unroll
        for (int l = 0; l < 16; ++l) { sq += Qp[l * 64]; sk += Kp[l * 64]; }
        qm[((size_t)h * 64 + blk) * 64 + d] = sq * 0.0625f;
        km[((size_t)h * 64 + blk) * 64 + d] = sk * 0.0625f;
    }
}

// ---------------------------------------------------------------------------
// btopk: block scores + causal top-8 bitmask (validated r12-r14).
// ---------------------------------------------------------------------------
__global__ __launch_bounds__(256)
void btopk_kernel(const float* __restrict__ qm, const float* __restrict__ km,
                  unsigned long long* __restrict__ maskbits)
{
    int h = blockIdx.x, tid = threadIdx.x;
    __shared__ float qs[64][64];
    __shared__ float kmT[64][64];
    __shared__ float sc[64][64];

    for (int idx = tid; idx < 4096; idx += 256) {
        int blk = idx >> 6, d = idx & 63;
        qs[blk][d] = qm[((size_t)h * 64 + blk) * 64 + d];
        kmT[d][blk] = km[((size_t)h * 64 + blk) * 64 + d];
    }
    __syncthreads();
    for (int idx = tid; idx < 4096; idx += 256) {
        int r = idx >> 6, c = idx & 63;
        float s = 0.f;
#pragma unroll
        for (int d = 0; d < 64; ++d) s += qs[r][d] * kmT[d][c];
        sc[r][c] = s;
    }
    __syncthreads();
    if (tid < 64) {
        int r = tid;
        unsigned long long bits = 0ull;
        int nsel = (r + 1 < 8) ? (r + 1) : 8;
        for (int sel = 0; sel < nsel; ++sel) {
            float best = -1e38f; int bi = 0;
            for (int kb = 0; kb <= r; ++kb) {
                float v = sc[r][kb];
                if (v > best) { best = v; bi = kb; }
            }
            sc[r][bi] = -1e38f;
            bits |= (1ull << bi);
        }
        maskbits[h * NB + r] = bits;
    }
}

// ---------------------------------------------------------------------------
// Sparse flash attention on tensor cores (validated r8-r14).
// ---------------------------------------------------------------------------
__global__ __launch_bounds__(128)
void attn_mma(const float* __restrict__ Q, const float* __restrict__ K,
              const float* __restrict__ Vraw, const unsigned long long* __restrict__ maskbits,
              const float* __restrict__ sink_scalars, const float* __restrict__ v_nulls,
              float* __restrict__ ctx)
{
    int warp = threadIdx.x >> 5, lane = threadIdx.x & 31;
    int g = lane >> 2, tg = lane & 3;
    int idx = blockIdx.x * 4 + warp;
    int h = idx >> 6, qb = idx & 63;
    int s = h & 7;
    __shared__ __align__(16) float Ksm[4][16][68];
    __shared__ __align__(16) float Vsm[4][16][68];
    __shared__ float psm[4][16][20];

    uint32_t qh[8][4], ql[8][4];
    {
        const float* Qp = Q + ((size_t)h * T_TOK + qb * 16) * 64;
#pragma unroll
        for (int ks = 0; ks < 8; ++ks) {
            float a0 = Qp[g * 64 + ks * 8 + tg];
            float a1 = Qp[(g + 8) * 64 + ks * 8 + tg];
            float a2 = Qp[g * 64 + ks * 8 + tg + 4];
            float a3 = Qp[(g + 8) * 64 + ks * 8 + tg + 4];
            float h0 = tf32r(a0), h1 = tf32r(a1), h2 = tf32r(a2), h3 = tf32r(a3);
            qh[ks][0] = __float_as_uint(h0); ql[ks][0] = __float_as_uint(tf32r(a0 - h0));
            qh[ks][1] = __float_as_uint(h1); ql[ks][1] = __float_as_uint(tf32r(a1 - h1));
            qh[ks][2] = __float_as_uint(h2); ql[ks][2] = __float_as_uint(tf32r(a2 - h2));
            qh[ks][3] = __float_as_uint(h3); ql[ks][3] = __float_as_uint(tf32r(a3 - h3));
        }
    }

    float c[8][4];
#pragma unroll
    for (int nt = 0; nt < 8; ++nt)
#pragma unroll
        for (int r = 0; r < 4; ++r) c[nt][r] = 0.f;

    float m0 = NEGBIG, m1 = NEGBIG, l0 = 0.f, l1 = 0.f;
    unsigned long long bm = maskbits[h * NB + qb];
    int i0 = qb * 16 + g, i1 = i0 + 8;

    for (int kb = 0; kb <= qb; ++kb) {
        bool blk_ok = ((bm >> kb) & 1ull) || (kb < 4) || (kb == qb);
        if (!blk_ok && kb != qb - 1) continue;

        {
            const float* Kp = K + ((size_t)h * T_TOK + kb * 16) * 64;
            const float* Vp = Vraw + (size_t)(kb * 16) * 512 + s * 64;
            __syncwarp();
#pragma unroll
            for (int i = 0; i < 8; ++i) {
                int lin = i * 32 + lane;
                int row = lin >> 4, c4 = (lin & 15) << 2;
                *reinterpret_cast<float4*>(&Ksm[warp][row][c4]) =
                    *reinterpret_cast<const float4*>(Kp + row * 64 + c4);
                *reinterpret_cast<float4*>(&Vsm[warp][row][c4]) =
                    *reinterpret_cast<const float4*>(Vp + (size_t)row * 512 + c4);
            }
            __syncwarp();
        }

        float sc[2][4];
#pragma unroll
        for (int nt = 0; nt < 2; ++nt)
#pragma unroll
            for (int r = 0; r < 4; ++r) sc[nt][r] = 0.f;

#pragma unroll
        for (int ks = 0; ks < 8; ++ks) {
#pragma unroll
            for (int nt = 0; nt < 2; ++nt) {
                float b0f = Ksm[warp][nt * 8 + g][ks * 8 + tg];
                float b1f = Ksm[warp][nt * 8 + g][ks * 8 + tg + 4];
                float bh0 = tf32r(b0f), bh1 = tf32r(b1f);
                uint32_t bh[2] = { __float_as_uint(bh0), __float_as_uint(bh1) };
                uint32_t bl[2] = { __float_as_uint(tf32r(b0f - bh0)),
                                   __float_as_uint(tf32r(b1f - bh1)) };
                mma8(sc[nt], qh[ks], bh);
                mma8(sc[nt], qh[ks], bl);
                mma8(sc[nt], ql[ks], bh);
            }
        }

#pragma unroll
        for (int nt = 0; nt < 2; ++nt)
#pragma unroll
            for (int r = 0; r < 4; ++r) {
                int j = kb * 16 + nt * 8 + 2 * tg + (r & 1);
                int i = (r < 2) ? i0 : i1;
                float v = sc[nt][r] * 0.125f;
                bool valid = (j <= i) && (blk_ok || (j >= i - 16));
                sc[nt][r] = valid ? v : NEGBIG;
            }

        float mx0 = fmaxf(fmaxf(sc[0][0], sc[0][1]), fmaxf(sc[1][0], sc[1][1]));
        float mx1 = fmaxf(fmaxf(sc[0][2], sc[0][3]), fmaxf(sc[1][2], sc[1][3]));
        mx0 = fmaxf(mx0, __shfl_xor_sync(0xffffffffu, mx0, 1));
        mx0 = fmaxf(mx0, __shfl_xor_sync(0xffffffffu, mx0, 2));
        mx1 = fmaxf(mx1, __shfl_xor_sync(0xffffffffu, mx1, 1));
        mx1 = fmaxf(mx1, __shfl_xor_sync(0xffffffffu, mx1, 2));
        float mn0 = fmaxf(m0, mx0), mn1 = fmaxf(m1, mx1);
        float al0 = __expf(m0 - mn0), al1 = __expf(m1 - mn1);
        m0 = mn0; m1 = mn1;

        float p[2][4];
#pragma unroll
        for (int nt = 0; nt < 2; ++nt) {
            p[nt][0] = __expf(sc[nt][0] - mn0);
            p[nt][1] = __expf(sc[nt][1] - mn0);
            p[nt][2] = __expf(sc[nt][2] - mn1);
            p[nt][3] = __expf(sc[nt][3] - mn1);
        }
        float s0 = p[0][0] + p[0][1] + p[1][0] + p[1][1];
        float s1 = p[0][2] + p[0][3] + p[1][2] + p[1][3];
        s0 += __shfl_xor_sync(0xffffffffu, s0, 1);
        s0 += __shfl_xor_sync(0xffffffffu, s0, 2);
        s1 += __shfl_xor_sync(0xffffffffu, s1, 1);
        s1 += __shfl_xor_sync(0xffffffffu, s1, 2);
        l0 = l0 * al0 + s0;
        l1 = l1 * al1 + s1;

#pragma unroll
        for (int nt = 0; nt < 8; ++nt) {
            c[nt][0] *= al0; c[nt][1] *= al0;
            c[nt][2] *= al1; c[nt][3] *= al1;
        }

        __syncwarp();
#pragma unroll
        for (int nt = 0; nt < 2; ++nt) {
            psm[warp][g][nt * 8 + 2 * tg]         = p[nt][0];
            psm[warp][g][nt * 8 + 2 * tg + 1]     = p[nt][1];
            psm[warp][g + 8][nt * 8 + 2 * tg]     = p[nt][2];
            psm[warp][g + 8][nt * 8 + 2 * tg + 1] = p[nt][3];
        }
        __syncwarp();
        uint32_t pah[2][4], pal[2][4];
#pragma unroll
        for (int ks = 0; ks < 2; ++ks) {
            float a0 = psm[warp][g][ks * 8 + tg];
            float a1 = psm[warp][g + 8][ks * 8 + tg];
            float a2 = psm[warp][g][ks * 8 + tg + 4];
            float a3 = psm[warp][g + 8][ks * 8 + tg + 4];
            float h0 = tf32r(a0), h1 = tf32r(a1), h2 = tf32r(a2), h3 = tf32r(a3);
            pah[ks][0] = __float_as_uint(h0); pal[ks][0] = __float_as_uint(tf32r(a0 - h0));
            pah[ks][1] = __float_as_uint(h1); pal[ks][1] = __float_as_uint(tf32r(a1 - h1));
            pah[ks][2] = __float_as_uint(h2); pal[ks][2] = __float_as_uint(tf32r(a2 - h2));
            pah[ks][3] = __float_as_uint(h3); pal[ks][3] = __float_as_uint(tf32r(a3 - h3));
        }

#pragma unroll
        for (int nt = 0; nt < 8; ++nt) {
#pragma unroll
            for (int ks = 0; ks < 2; ++ks) {
                float b0f = Vsm[warp][ks * 8 + tg][nt * 8 + g];
                float b1f = Vsm[warp][ks * 8 + tg + 4][nt * 8 + g];
                float bh0 = tf32r(b0f), bh1 = tf32r(b1f);
                uint32_t bh[2] = { __float_as_uint(bh0), __float_as_uint(bh1) };
                uint32_t bl[2] = { __float_as_uint(tf32r(b0f - bh0)),
                                   __float_as_uint(tf32r(b1f - bh1)) };
                mma8(c[nt], pah[ks], bh);
                mma8(c[nt], pah[ks], bl);
                mma8(c[nt], pal[ks], bh);
            }
        }
    }

    float sv = sink_scalars[h];
    float fn0 = fmaxf(m0, sv), fn1 = fmaxf(m1, sv);
    float fa0 = __expf(m0 - fn0), fa1 = __expf(m1 - fn1);
    float pk0 = __expf(sv - fn0), pk1 = __expf(sv - fn1);
    float inv0 = 1.f / (l0 * fa0 + pk0);
    float inv1 = 1.f / (l1 * fa1 + pk1);
    const float* vn = v_nulls + h * 64;
#pragma unroll
    for (int nt = 0; nt < 8; ++nt) {
        int col = nt * 8 + 2 * tg;
        float vn0 = vn[col], vn1 = vn[col + 1];
        float* op0 = ctx + (size_t)(qb * 16 + g) * 4096 + h * 64 + col;
        float* op1 = ctx + (size_t)(qb * 16 + g + 8) * 4096 + h * 64 + col;
        *reinterpret_cast<float2*>(op0) =
            make_float2((c[nt][0] * fa0 + pk0 * vn0) * inv0,
                        (c[nt][1] * fa0 + pk0 * vn1) * inv0);
        *reinterpret_cast<float2*>(op1) =
            make_float2((c[nt][2] * fa1 + pk1 * vn0) * inv1,
                        (c[nt][3] * fa1 + pk1 * vn1) * inv1);
    }
}

// ---------------------------------------------------------------------------
__global__ void reduce_out(const float* __restrict__ part, const float* __restrict__ WOb,
                           float* __restrict__ out)
{
    int idx = blockIdx.x * 256 + threadIdx.x;
    int col = idx & 511;
    float b = 0.f;
#pragma unroll
    for (int n = 0; n < 8; ++n) b += WOb[n * 512 + col];
    const int S = T_TOK * 512;
    out[idx] = 0.125f * (part[idx] + part[S + idx] + part[2 * S + idx] + part[3 * S + idx] + b);
}

// ---------------------------------------------------------------------------
extern "C" void kernel_launch(void* const* d_in, const int* in_sizes, int n_in,
                              void* d_out, int out_size)
{
    const float* x   = (const float*)d_in[0];
    const float* WQ  = (const float*)d_in[1];
    const float* WK  = (const float*)d_in[2];
    const float* bK  = (const float*)d_in[3];
    const float* WV  = (const float*)d_in[4];
    const float* bV  = (const float*)d_in[5];
    const float* Am  = (const float*)d_in[6];
    const float* idb = (const float*)d_in[7];
    const float* snk = (const float*)d_in[8];
    const float* vnl = (const float*)d_in[9];
    const float* WO  = (const float*)d_in[10];
    const float* WOb = (const float*)d_in[11];
    float* out = (float*)d_out;

    float *weff, *kraw, *vraw, *Qb, *Kb, *qmb, *kmb, *ctx, *part;
    unsigned long long* mb;
    cudaGetSymbolAddress((void**)&weff, g_Weff);
    cudaGetSymbolAddress((void**)&kraw, g_kraw);
    cudaGetSymbolAddress((void**)&vraw, g_vraw);
    cudaGetSymbolAddress((void**)&Qb,   g_Q);
    cudaGetSymbolAddress((void**)&Kb,   g_K);
    cudaGetSymbolAddress((void**)&qmb,  g_qm);
    cudaGetSymbolAddress((void**)&kmb,  g_km);
    cudaGetSymbolAddress((void**)&ctx,  g_ctx);
    cudaGetSymbolAddress((void**)&part, g_part);
    cudaGetSymbolAddress((void**)&mb,   g_mask);

    // launches 1-3 (ncu -s 5 -c 1 captures launch #4 = qkv_gemm)
    prep_cs<<<128, 256>>>();
    prep_fold<<<dim3(64, 4), 128>>>(Am, idb, WQ, weff, 0);
    prep_fold<<<dim3(64, 4), 128>>>(Am, idb, WQ, weff, 4);

    // launch 4: profiled
    qkv_gemm<<<dim3(40, 8), 512>>>(x, weff, WK, WV, bK, bV, Qb, kraw, vraw);

    km_krope<<<dim3(8, 8), 256>>>(Am, idb, kraw, Kb);

    bmeans_kernel<<<dim3(64, 4), 256>>>(Qb, Kb, qmb, kmb);
    btopk_kernel<<<64, 256>>>(qmb, kmb, mb);

    attn_mma<<<1024, 128>>>(Qb, Kb, vraw, mb, snk, vnl, ctx);

    mma_gemm_nn<4><<<dim3(4, 8, 4), 256>>>(ctx, WO, part, 1024, 512, 4096);
    reduce_out<<<2048, 256>>>(part, WOb, out);
}

// round 16
// speedup vs baseline: 1.0334x; 1.0334x over previous
#include <cuda_runtime.h>
#include <cuda_bf16.h>
#include <cstdint>

// ---------------------------------------------------------------------------
// SSA attention, 3xTF32 pipeline, v16.
//  v16: qkv_gemm stores RAW fp32 in smem (2 buffers) and computes the 3xTF32
//  hi/lo split on the fly at fragment load (like attn_mma does). r15 ncu
//  showed qkv is LDS-bound (L1 64%, ALU 10%): pre-split hi/lo doubled smem
//  traffic. 256 threads (r13/r14-validated layout). Bit-identical math.
// ---------------------------------------------------------------------------

#define T_TOK   1024
#define NB      64
#define NEGBIG  (-1e30f)

__device__ float g_Weff[4096 * 512];
__device__ float2 g_cs[1024 * 32];      // (cos, sin) per (token, freq)
__device__ float g_kraw[T_TOK * 512];
__device__ float g_vraw[T_TOK * 512];
__device__ float g_Q[64 * T_TOK * 64];
__device__ float g_K[64 * T_TOK * 64];
__device__ float g_qm[64 * 64 * 64];
__device__ float g_km[64 * 64 * 64];
__device__ float g_ctx[T_TOK * 4096];
__device__ float g_part[4 * T_TOK * 512];
__device__ unsigned long long g_mask[64 * NB];

__device__ __forceinline__ float tf32r(float x) {
    uint32_t u;
    asm("cvt.rna.tf32.f32 %0, %1;" : "=r"(u) : "f"(x));
    return __uint_as_float(u);
}

__device__ __forceinline__ void mma8(float* c, const uint32_t* a, const uint32_t* b) {
    asm volatile(
        "mma.sync.aligned.m16n8k8.row.col.f32.tf32.tf32.f32 "
        "{%0,%1,%2,%3}, {%4,%5,%6,%7}, {%8,%9}, {%0,%1,%2,%3};"
        : "+f"(c[0]), "+f"(c[1]), "+f"(c[2]), "+f"(c[3])
        : "r"(a[0]), "r"(a[1]), "r"(a[2]), "r"(a[3]), "r"(b[0]), "r"(b[1]));
}

// hi/lo split helper: v -> (hi, lo) bit-identical to the pre-split path
__device__ __forceinline__ void hl(float v, uint32_t& hi, uint32_t& lo) {
    float h = tf32r(v);
    hi = __float_as_uint(h);
    lo = __float_as_uint(tf32r(v - h));
}

// ---------------------------------------------------------------------------
__global__ void prep_cs()
{
    int idx = blockIdx.x * 256 + threadIdx.x;   // 32768 entries
    int f = idx & 31;
    int t = idx >> 5;
    float iv = (float)exp(-9.210340371976184 * (double)f / 32.0);
    float sn, cs;
    sincosf((float)t * iv, &sn, &cs);
    g_cs[idx] = make_float2(cs, sn);
}

// ---------------------------------------------------------------------------
// Q weight folding, 3xTF32 (validated r5-r15). Launched twice (cgbase 0/4).
// ---------------------------------------------------------------------------
__global__ __launch_bounds__(128)
void prep_fold(const float* __restrict__ A, const float* __restrict__ idb,
               const float* __restrict__ WQ, float* __restrict__ Weff, int cgbase)
{
    int h = blockIdx.x, cg = cgbase + blockIdx.y;
    int tid = threadIdx.x;
    int warp = tid >> 5, lane = tid & 31;
    int g = lane >> 2, tg = lane & 3;
    __shared__ float Th[64][64], Tl[64][64];
    __shared__ float Wh[64][32], Wl[64][32];

    for (int idx = tid; idx < 4096; idx += 128) {
        int e = idx >> 6, d = idx & 63;
        float v = A[d * 64 + e] - A[e * 64 + d];
        if (d == e) v += 1.f + idb[h * 64 + e];
        float hi = tf32r(v);
        Th[e][d] = hi;
        Tl[e][d] = tf32r(v - hi);
    }
    const float* Wsrc = WQ + (size_t)(h * 64) * 512;
    float* Wdst = Weff + (size_t)(h * 64) * 512;

    for (int chunk = cg * 2; chunk < cg * 2 + 2; ++chunk) {
        __syncthreads();
        for (int idx = tid; idx < 2048; idx += 128) {
            int d = idx >> 5, n = idx & 31;
            float v = Wsrc[(size_t)d * 512 + chunk * 32 + n];
            float hi = tf32r(v);
            Wh[d][n] = hi;
            Wl[d][n] = tf32r(v - hi);
        }
        __syncthreads();

        float c[4][4];
#pragma unroll
        for (int mt = 0; mt < 4; ++mt)
#pragma unroll
            for (int r = 0; r < 4; ++r) c[mt][r] = 0.f;

#pragma unroll
        for (int k0 = 0; k0 < 64; k0 += 8) {
            uint32_t ah[4][4], al[4][4], bh[2], bl[2];
#pragma unroll
            for (int mt = 0; mt < 4; ++mt) {
                int mb = mt * 16;
                ah[mt][0] = __float_as_uint(Th[mb + g][k0 + tg]);
                ah[mt][1] = __float_as_uint(Th[mb + g + 8][k0 + tg]);
                ah[mt][2] = __float_as_uint(Th[mb + g][k0 + tg + 4]);
                ah[mt][3] = __float_as_uint(Th[mb + g + 8][k0 + tg + 4]);
                al[mt][0] = __float_as_uint(Tl[mb + g][k0 + tg]);
                al[mt][1] = __float_as_uint(Tl[mb + g + 8][k0 + tg]);
                al[mt][2] = __float_as_uint(Tl[mb + g][k0 + tg + 4]);
                al[mt][3] = __float_as_uint(Tl[mb + g + 8][k0 + tg + 4]);
            }
            int nb = warp * 8;
            bh[0] = __float_as_uint(Wh[k0 + tg][nb + g]);
            bh[1] = __float_as_uint(Wh[k0 + tg + 4][nb + g]);
            bl[0] = __float_as_uint(Wl[k0 + tg][nb + g]);
            bl[1] = __float_as_uint(Wl[k0 + tg + 4][nb + g]);
#pragma unroll
            for (int mt = 0; mt < 4; ++mt) {
                mma8(c[mt], ah[mt], bh);
                mma8(c[mt], ah[mt], bl);
                mma8(c[mt], al[mt], bh);
            }
        }
#pragma unroll
        for (int mt = 0; mt < 4; ++mt) {
            int row = mt * 16 + g;
            int col = chunk * 32 + warp * 8 + 2 * tg;
            *reinterpret_cast<float2*>(Wdst + (size_t)row * 512 + col)
                = make_float2(c[mt][0], c[mt][1]);
            *reinterpret_cast<float2*>(Wdst + (size_t)(row + 8) * 512 + col)
                = make_float2(c[mt][2], c[mt][3]);
        }
    }
}

// ---------------------------------------------------------------------------
// QKV projection, 3xTF32, v16: 256 threads, RAW fp32 smem, on-the-fly hi/lo.
// Same 128x128 tile, same k-order -> bit-identical results.
// ---------------------------------------------------------------------------
__global__ __launch_bounds__(256)
void qkv_gemm(const float* __restrict__ Ag, const float* __restrict__ Weff,
              const float* __restrict__ WKw, const float* __restrict__ WVw,
              const float* __restrict__ bK, const float* __restrict__ bV,
              float* __restrict__ Qo, float* __restrict__ kraw, float* __restrict__ vraw)
{
    const int K = 512;
    __shared__ float As[16][132], Bs[16][132];
    int tid = threadIdx.x;
    int warp = tid >> 5, lane = tid & 31;
    int wm = warp >> 2, wn = warp & 3;
    int g = lane >> 2, tg = lane & 3;
    int m0 = blockIdx.y * 128, n0 = blockIdx.x * 128;

    const float* Bsrc;
    int nbase;
    if (n0 < 4096)      { Bsrc = Weff; nbase = n0; }
    else if (n0 < 4608) { Bsrc = WKw;  nbase = n0 - 4096; }
    else                { Bsrc = WVw;  nbase = n0 - 4608; }

    int rowA[2], kqA[2];
#pragma unroll
    for (int q = 0; q < 2; ++q) {
        int idx = q * 256 + tid;
        rowA[q] = idx >> 2;
        kqA[q]  = (idx & 3) << 2;
    }

    float c[4][4][4];
#pragma unroll
    for (int i = 0; i < 4; ++i)
#pragma unroll
        for (int j = 0; j < 4; ++j)
#pragma unroll
            for (int r = 0; r < 4; ++r) c[i][j][r] = 0.f;

    float4 pa[2], pb[2];
#pragma unroll
    for (int q = 0; q < 2; ++q) {
        pa[q] = *reinterpret_cast<const float4*>(Ag + (size_t)(m0 + rowA[q]) * K + kqA[q]);
        pb[q] = *reinterpret_cast<const float4*>(Bsrc + (size_t)(nbase + rowA[q]) * K + kqA[q]);
    }

    for (int k0 = 0; k0 < K; k0 += 16) {
#pragma unroll
        for (int q = 0; q < 2; ++q) {
            int row = rowA[q], kq = kqA[q];
            float4 a = pa[q];
            As[kq + 0][row] = a.x; As[kq + 1][row] = a.y;
            As[kq + 2][row] = a.z; As[kq + 3][row] = a.w;
            float4 b = pb[q];
            Bs[kq + 0][row] = b.x; Bs[kq + 1][row] = b.y;
            Bs[kq + 2][row] = b.z; Bs[kq + 3][row] = b.w;
        }
        __syncthreads();

        if (k0 + 16 < K) {
#pragma unroll
            for (int q = 0; q < 2; ++q) {
                pa[q] = *reinterpret_cast<const float4*>(
                    Ag + (size_t)(m0 + rowA[q]) * K + k0 + 16 + kqA[q]);
                pb[q] = *reinterpret_cast<const float4*>(
                    Bsrc + (size_t)(nbase + rowA[q]) * K + k0 + 16 + kqA[q]);
            }
        }

#pragma unroll
        for (int h8 = 0; h8 < 16; h8 += 8) {
            uint32_t afh[4][4], bfh[4][2];
            uint32_t afl[4][4], bfl[4][2];
#pragma unroll
            for (int mt = 0; mt < 4; ++mt) {
                int mb = wm * 64 + mt * 16;
                hl(As[h8 + tg][mb + g],         afh[mt][0], afl[mt][0]);
                hl(As[h8 + tg][mb + g + 8],     afh[mt][1], afl[mt][1]);
                hl(As[h8 + tg + 4][mb + g],     afh[mt][2], afl[mt][2]);
                hl(As[h8 + tg + 4][mb + g + 8], afh[mt][3], afl[mt][3]);
            }
#pragma unroll
            for (int nt = 0; nt < 4; ++nt) {
                int nb = wn * 32 + nt * 8;
                hl(Bs[h8 + tg][nb + g],     bfh[nt][0], bfl[nt][0]);
                hl(Bs[h8 + tg + 4][nb + g], bfh[nt][1], bfl[nt][1]);
            }
#pragma unroll
            for (int mt = 0; mt < 4; ++mt)
#pragma unroll
                for (int nt = 0; nt < 4; ++nt) {
                    mma8(c[mt][nt], afh[mt], bfh[nt]);
                    mma8(c[mt][nt], afh[mt], bfl[nt]);
                    mma8(c[mt][nt], afl[mt], bfh[nt]);
                }
        }
        __syncthreads();
    }

#pragma unroll
    for (int mt = 0; mt < 4; ++mt) {
        int row = m0 + wm * 64 + mt * 16 + g;
#pragma unroll
        for (int nt = 0; nt < 4; ++nt) {
            int col = n0 + wn * 32 + nt * 8 + 2 * tg;
            float c0 = c[mt][nt][0], c1 = c[mt][nt][1];
            float c2 = c[mt][nt][2], c3 = c[mt][nt][3];
            if (n0 < 4096) {
                int h = col >> 6, f = (col & 63) >> 1;
                float2 cs0 = g_cs[row * 32 + f];
                float2 cs1 = g_cs[(row + 8) * 32 + f];
                float* q0 = Qo + ((size_t)h * T_TOK + row) * 64;
                float* q1 = Qo + ((size_t)h * T_TOK + row + 8) * 64;
                q0[f]      = c0 * cs0.x - c1 * cs0.y;
                q0[f + 32] = c0 * cs0.y + c1 * cs0.x;
                q1[f]      = c2 * cs1.x - c3 * cs1.y;
                q1[f + 32] = c2 * cs1.y + c3 * cs1.x;
            } else if (n0 < 4608) {
                int cc = col - 4096;
                float b0 = bK[cc], b1 = bK[cc + 1];
                *reinterpret_cast<float2*>(kraw + (size_t)row * 512 + cc)
                    = make_float2(c0 + b0, c1 + b1);
                *reinterpret_cast<float2*>(kraw + (size_t)(row + 8) * 512 + cc)
                    = make_float2(c2 + b0, c3 + b1);
            } else {
                int cc = col - 4608;
                float b0 = bV[cc], b1 = bV[cc + 1];
                *reinterpret_cast<float2*>(vraw + (size_t)row * 512 + cc)
                    = make_float2(c0 + b0, c1 + b1);
                *reinterpret_cast<float2*>(vraw + (size_t)(row + 8) * 512 + cc)
                    = make_float2(c2 + b0, c3 + b1);
            }
        }
    }
}

// ---------------------------------------------------------------------------
// Fused K transform (validated r13-r15), rope tail reads g_cs LUT.
// ---------------------------------------------------------------------------
__global__ __launch_bounds__(256)
void km_krope(const float* __restrict__ A, const float* __restrict__ idb,
              const float* __restrict__ kraw, float* __restrict__ Ko)
{
    int rt = blockIdx.x, s = blockIdx.y;
    int tid = threadIdx.x;
    int warp = tid >> 5, lane = tid & 31;
    int g = lane >> 2, tg = lane & 3;
    __shared__ float Mh[64][64], Ml[64][64];

    for (int idx = tid; idx < 4096; idx += 256) {
        int d = idx >> 6, e = idx & 63;
        float v = A[d * 64 + e] - A[e * 64 + d];
        float hi = tf32r(v);
        Mh[d][e] = hi;
        Ml[d][e] = tf32r(v - hi);
    }
    __syncthreads();

    int t0 = rt * 128 + warp * 16;
    const float* Ap = kraw + (size_t)t0 * 512 + s * 64;

    float c[8][4];
#pragma unroll
    for (int nt = 0; nt < 8; ++nt)
#pragma unroll
        for (int r = 0; r < 4; ++r) c[nt][r] = 0.f;

#pragma unroll
    for (int k0 = 0; k0 < 64; k0 += 8) {
        float a0 = Ap[(size_t)g * 512 + k0 + tg];
        float a1 = Ap[(size_t)(g + 8) * 512 + k0 + tg];
        float a2 = Ap[(size_t)g * 512 + k0 + tg + 4];
        float a3 = Ap[(size_t)(g + 8) * 512 + k0 + tg + 4];
        uint32_t ah[4], al[4];
        hl(a0, ah[0], al[0]);
        hl(a1, ah[1], al[1]);
        hl(a2, ah[2], al[2]);
        hl(a3, ah[3], al[3]);
#pragma unroll
        for (int nt = 0; nt < 8; ++nt) {
            uint32_t bh[2], bl[2];
            int nb = nt * 8;
            bh[0] = __float_as_uint(Mh[k0 + tg][nb + g]);
            bh[1] = __float_as_uint(Mh[k0 + tg + 4][nb + g]);
            bl[0] = __float_as_uint(Ml[k0 + tg][nb + g]);
            bl[1] = __float_as_uint(Ml[k0 + tg + 4][nb + g]);
            mma8(c[nt], ah, bh);
            mma8(c[nt], ah, bl);
            mma8(c[nt], al, bh);
        }
    }

    int ta = t0 + g, tb = ta + 8;
    float snA[8], csA[8], snB[8], csB[8];
    float kA0[8], kA1[8], kB0[8], kB1[8];
#pragma unroll
    for (int nt = 0; nt < 8; ++nt) {
        int f = nt * 4 + tg;
        float2 cA = g_cs[ta * 32 + f];
        float2 cB = g_cs[tb * 32 + f];
        csA[nt] = cA.x; snA[nt] = cA.y;
        csB[nt] = cB.x; snB[nt] = cB.y;
        int col = nt * 8 + 2 * tg;
        kA0[nt] = kraw[(size_t)ta * 512 + s * 64 + col];
        kA1[nt] = kraw[(size_t)ta * 512 + s * 64 + col + 1];
        kB0[nt] = kraw[(size_t)tb * 512 + s * 64 + col];
        kB1[nt] = kraw[(size_t)tb * 512 + s * 64 + col + 1];
    }

#pragma unroll
    for (int hh = 0; hh < 8; ++hh) {
        int h = hh * 8 + s;
        float* koA = Ko + ((size_t)h * T_TOK + ta) * 64;
        float* koB = Ko + ((size_t)h * T_TOK + tb) * 64;
#pragma unroll
        for (int nt = 0; nt < 8; ++nt) {
            int col = nt * 8 + 2 * tg;
            int f = nt * 4 + tg;
            float ib0 = 1.f + idb[h * 64 + col];
            float ib1 = 1.f + idb[h * 64 + col + 1];
            float vA0 = c[nt][0] + kA0[nt] * ib0;
            float vA1 = c[nt][1] + kA1[nt] * ib1;
            float vB0 = c[nt][2] + kB0[nt] * ib0;
            float vB1 = c[nt][3] + kB1[nt] * ib1;
            koA[f]      = vA0 * csA[nt] - vA1 * snA[nt];
            koA[f + 32] = vA0 * snA[nt] + vA1 * csA[nt];
            koB[f]      = vB0 * csB[nt] - vB1 * snB[nt];
            koB[f + 32] = vB0 * snB[nt] + vB1 * csB[nt];
        }
    }
}

// ---------------------------------------------------------------------------
// Output projection, single tf32, split-K, register prefetch (validated).
// ---------------------------------------------------------------------------
template<int SPLITK>
__global__ __launch_bounds__(256)
void mma_gemm_nn(const float* __restrict__ Ag, const float* __restrict__ Bg,
                 float* __restrict__ Cg, int M, int N, int K)
{
    __shared__ float As[16][132];
    __shared__ float Bs[16][132];
    int tid = threadIdx.x;
    int warp = tid >> 5, lane = tid & 31;
    int wm = warp >> 2, wn = warp & 3;
    int g = lane >> 2, tg = lane & 3;
    int m0 = blockIdx.y * 128, n0 = blockIdx.x * 128;
    int kchunk = K / SPLITK;
    int kbeg = blockIdx.z * kchunk;
    int kend = kbeg + kchunk;

    int rowA[2], kqA[2], rB[2], cB[2];
#pragma unroll
    for (int q = 0; q < 2; ++q) {
        int idx = q * 256 + tid;
        rowA[q] = idx >> 2; kqA[q] = (idx & 3) << 2;
        rB[q] = idx >> 5;   cB[q]  = (idx & 31) << 2;
    }

    float c[4][4][4];
#pragma unroll
    for (int i = 0; i < 4; ++i)
#pragma unroll
        for (int j = 0; j < 4; ++j)
#pragma unroll
            for (int r = 0; r < 4; ++r) c[i][j][r] = 0.f;

    float4 pa[2], pb[2];
#pragma unroll
    for (int q = 0; q < 2; ++q) {
        pa[q] = *reinterpret_cast<const float4*>(Ag + (size_t)(m0 + rowA[q]) * K + kbeg + kqA[q]);
        pb[q] = *reinterpret_cast<const float4*>(Bg + (size_t)(kbeg + rB[q]) * N + n0 + cB[q]);
    }

    for (int k0 = kbeg; k0 < kend; k0 += 16) {
#pragma unroll
        for (int q = 0; q < 2; ++q) {
            int row = rowA[q], kq = kqA[q];
            float4 a = pa[q];
            As[kq + 0][row] = tf32r(a.x); As[kq + 1][row] = tf32r(a.y);
            As[kq + 2][row] = tf32r(a.z); As[kq + 3][row] = tf32r(a.w);
            float4 b = pb[q];
            Bs[rB[q]][cB[q] + 0] = tf32r(b.x); Bs[rB[q]][cB[q] + 1] = tf32r(b.y);
            Bs[rB[q]][cB[q] + 2] = tf32r(b.z); Bs[rB[q]][cB[q] + 3] = tf32r(b.w);
        }
        __syncthreads();

        if (k0 + 16 < kend) {
#pragma unroll
            for (int q = 0; q < 2; ++q) {
                pa[q] = *reinterpret_cast<const float4*>(
                    Ag + (size_t)(m0 + rowA[q]) * K + k0 + 16 + kqA[q]);
                pb[q] = *reinterpret_cast<const float4*>(
                    Bg + (size_t)(k0 + 16 + rB[q]) * N + n0 + cB[q]);
            }
        }

#pragma unroll
        for (int h8 = 0; h8 < 16; h8 += 8) {
            uint32_t af[4][4], bf[4][2];
#pragma unroll
            for (int mt = 0; mt < 4; ++mt) {
                int mb = wm * 64 + mt * 16;
                af[mt][0] = __float_as_uint(As[h8 + tg][mb + g]);
                af[mt][1] = __float_as_uint(As[h8 + tg][mb + g + 8]);
                af[mt][2] = __float_as_uint(As[h8 + tg + 4][mb + g]);
                af[mt][3] = __float_as_uint(As[h8 + tg + 4][mb + g + 8]);
            }
#pragma unroll
            for (int nt = 0; nt < 4; ++nt) {
                int nb = wn * 32 + nt * 8;
                bf[nt][0] = __float_as_uint(Bs[h8 + tg][nb + g]);
                bf[nt][1] = __float_as_uint(Bs[h8 + tg + 4][nb + g]);
            }
#pragma unroll
            for (int mt = 0; mt < 4; ++mt)
#pragma unroll
                for (int nt = 0; nt < 4; ++nt) mma8(c[mt][nt], af[mt], bf[nt]);
        }
        __syncthreads();
    }

    float* Cp = Cg + (size_t)blockIdx.z * M * N;
#pragma unroll
    for (int mt = 0; mt < 4; ++mt) {
        int row = m0 + wm * 64 + mt * 16 + g;
#pragma unroll
        for (int nt = 0; nt < 4; ++nt) {
            int col = n0 + wn * 32 + nt * 8 + 2 * tg;
            *reinterpret_cast<float2*>(Cp + (size_t)row * N + col)
                = make_float2(c[mt][nt][0], c[mt][nt][1]);
            *reinterpret_cast<float2*>(Cp + (size_t)(row + 8) * N + col)
                = make_float2(c[mt][nt][2], c[mt][nt][3]);
        }
    }
}

// ---------------------------------------------------------------------------
// bmeans: 16-token block means of Q and K (validated r12-r15).
// ---------------------------------------------------------------------------
__global__ __launch_bounds__(256)
void bmeans_kernel(const float* __restrict__ Q, const float* __restrict__ K,
                   float* __restrict__ qm, float* __restrict__ km)
{
    int h = blockIdx.x, quarter = blockIdx.y;
    int tid = threadIdx.x;
    for (int it = 0; it < 4; ++it) {
        int idx = it * 256 + tid;
        int blk = quarter * 16 + (idx >> 6);
        int d = idx & 63;
        const float* Qp = Q + ((size_t)h * T_TOK + blk * 16) * 64 + d;
        const float* Kp = K + ((size_t)h * T_TOK + blk * 16) * 64 + d;
        float sq = 0.f, sk = 0.f;
#pragma unroll
        for (int l = 0; l < 16; ++l) { sq += Qp[l * 64]; sk += Kp[l * 64]; }
        qm[((size_t)h * 64 + blk) * 64 + d] = sq * 0.0625f;
        km[((size_t)h * 64 + blk) * 64 + d] = sk * 0.0625f;
    }
}

// ---------------------------------------------------------------------------
// btopk: block scores + causal top-8 bitmask (validated r12-r15).
// ---------------------------------------------------------------------------
__global__ __launch_bounds__(256)
void btopk_kernel(const float* __restrict__ qm, const float* __restrict__ km,
                  unsigned long long* __restrict__ maskbits)
{
    int h = blockIdx.x, tid = threadIdx.x;
    __shared__ float qs[64][64];
    __shared__ float kmT[64][64];
    __shared__ float sc[64][64];

    for (int idx = tid; idx < 4096; idx += 256) {
        int blk = idx >> 6, d = idx & 63;
        qs[blk][d] = qm[((size_t)h * 64 + blk) * 64 + d];
        kmT[d][blk] = km[((size_t)h * 64 + blk) * 64 + d];
    }
    __syncthreads();
    for (int idx = tid; idx < 4096; idx += 256) {
        int r = idx >> 6, c = idx & 63;
        float s = 0.f;
#pragma unroll
        for (int d = 0; d < 64; ++d) s += qs[r][d] * kmT[d][c];
        sc[r][c] = s;
    }
    __syncthreads();
    if (tid < 64) {
        int r = tid;
        unsigned long long bits = 0ull;
        int nsel = (r + 1 < 8) ? (r + 1) : 8;
        for (int sel = 0; sel < nsel; ++sel) {
            float best = -1e38f; int bi = 0;
            for (int kb = 0; kb <= r; ++kb) {
                float v = sc[r][kb];
                if (v > best) { best = v; bi = kb; }
            }
            sc[r][bi] = -1e38f;
            bits |= (1ull << bi);
        }
        maskbits[h * NB + r] = bits;
    }
}

// ---------------------------------------------------------------------------
// Sparse flash attention on tensor cores (validated r8-r15).
// ---------------------------------------------------------------------------
__global__ __launch_bounds__(128)
void attn_mma(const float* __restrict__ Q, const float* __restrict__ K,
              const float* __restrict__ Vraw, const unsigned long long* __restrict__ maskbits,
              const float* __restrict__ sink_scalars, const float* __restrict__ v_nulls,
              float* __restrict__ ctx)
{
    int warp = threadIdx.x >> 5, lane = threadIdx.x & 31;
    int g = lane >> 2, tg = lane & 3;
    int idx = blockIdx.x * 4 + warp;
    int h = idx >> 6, qb = idx & 63;
    int s = h & 7;
    __shared__ __align__(16) float Ksm[4][16][68];
    __shared__ __align__(16) float Vsm[4][16][68];
    __shared__ float psm[4][16][20];

    uint32_t qh[8][4], ql[8][4];
    {
        const float* Qp = Q + ((size_t)h * T_TOK + qb * 16) * 64;
#pragma unroll
        for (int ks = 0; ks < 8; ++ks) {
            hl(Qp[g * 64 + ks * 8 + tg],           qh[ks][0], ql[ks][0]);
            hl(Qp[(g + 8) * 64 + ks * 8 + tg],     qh[ks][1], ql[ks][1]);
            hl(Qp[g * 64 + ks * 8 + tg + 4],       qh[ks][2], ql[ks][2]);
            hl(Qp[(g + 8) * 64 + ks * 8 + tg + 4], qh[ks][3], ql[ks][3]);
        }
    }

    float c[8][4];
#pragma unroll
    for (int nt = 0; nt < 8; ++nt)
#pragma unroll
        for (int r = 0; r < 4; ++r) c[nt][r] = 0.f;

    float m0 = NEGBIG, m1 = NEGBIG, l0 = 0.f, l1 = 0.f;
    unsigned long long bm = maskbits[h * NB + qb];
    int i0 = qb * 16 + g, i1 = i0 + 8;

    for (int kb = 0; kb <= qb; ++kb) {
        bool blk_ok = ((bm >> kb) & 1ull) || (kb < 4) || (kb == qb);
        if (!blk_ok && kb != qb - 1) continue;

        {
            const float* Kp = K + ((size_t)h * T_TOK + kb * 16) * 64;
            const float* Vp = Vraw + (size_t)(kb * 16) * 512 + s * 64;
            __syncwarp();
#pragma unroll
            for (int i = 0; i < 8; ++i) {
                int lin = i * 32 + lane;
                int row = lin >> 4, c4 = (lin & 15) << 2;
                *reinterpret_cast<float4*>(&Ksm[warp][row][c4]) =
                    *reinterpret_cast<const float4*>(Kp + row * 64 + c4);
                *reinterpret_cast<float4*>(&Vsm[warp][row][c4]) =
                    *reinterpret_cast<const float4*>(Vp + (size_t)row * 512 + c4);
            }
            __syncwarp();
        }

        float sc[2][4];
#pragma unroll
        for (int nt = 0; nt < 2; ++nt)
#pragma unroll
            for (int r = 0; r < 4; ++r) sc[nt][r] = 0.f;

#pragma unroll
        for (int ks = 0; ks < 8; ++ks) {
#pragma unroll
            for (int nt = 0; nt < 2; ++nt) {
                uint32_t bh[2], bl[2];
                hl(Ksm[warp][nt * 8 + g][ks * 8 + tg],     bh[0], bl[0]);
                hl(Ksm[warp][nt * 8 + g][ks * 8 + tg + 4], bh[1], bl[1]);
                mma8(sc[nt], qh[ks], bh);
                mma8(sc[nt], qh[ks], bl);
                mma8(sc[nt], ql[ks], bh);
            }
        }

#pragma unroll
        for (int nt = 0; nt < 2; ++nt)
#pragma unroll
            for (int r = 0; r < 4; ++r) {
                int j = kb * 16 + nt * 8 + 2 * tg + (r & 1);
                int i = (r < 2) ? i0 : i1;
                float v = sc[nt][r] * 0.125f;
                bool valid = (j <= i) && (blk_ok || (j >= i - 16));
                sc[nt][r] = valid ? v : NEGBIG;
            }

        float mx0 = fmaxf(fmaxf(sc[0][0], sc[0][1]), fmaxf(sc[1][0], sc[1][1]));
        float mx1 = fmaxf(fmaxf(sc[0][2], sc[0][3]), fmaxf(sc[1][2], sc[1][3]));
        mx0 = fmaxf(mx0, __shfl_xor_sync(0xffffffffu, mx0, 1));
        mx0 = fmaxf(mx0, __shfl_xor_sync(0xffffffffu, mx0, 2));
        mx1 = fmaxf(mx1, __shfl_xor_sync(0xffffffffu, mx1, 1));
        mx1 = fmaxf(mx1, __shfl_xor_sync(0xffffffffu, mx1, 2));
        float mn0 = fmaxf(m0, mx0), mn1 = fmaxf(m1, mx1);
        float al0 = __expf(m0 - mn0), al1 = __expf(m1 - mn1);
        m0 = mn0; m1 = mn1;

        float p[2][4];
#pragma unroll
        for (int nt = 0; nt < 2; ++nt) {
            p[nt][0] = __expf(sc[nt][0] - mn0);
            p[nt][1] = __expf(sc[nt][1] - mn0);
            p[nt][2] = __expf(sc[nt][2] - mn1);
            p[nt][3] = __expf(sc[nt][3] - mn1);
        }
        float s0 = p[0][0] + p[0][1] + p[1][0] + p[1][1];
        float s1 = p[0][2] + p[0][3] + p[1][2] + p[1][3];
        s0 += __shfl_xor_sync(0xffffffffu, s0, 1);
        s0 += __shfl_xor_sync(0xffffffffu, s0, 2);
        s1 += __shfl_xor_sync(0xffffffffu, s1, 1);
        s1 += __shfl_xor_sync(0xffffffffu, s1, 2);
        l0 = l0 * al0 + s0;
        l1 = l1 * al1 + s1;

#pragma unroll
        for (int nt = 0; nt < 8; ++nt) {
            c[nt][0] *= al0; c[nt][1] *= al0;
            c[nt][2] *= al1; c[nt][3] *= al1;
        }

        __syncwarp();
#pragma unroll
        for (int nt = 0; nt < 2; ++nt) {
            psm[warp][g][nt * 8 + 2 * tg]         = p[nt][0];
            psm[warp][g][nt * 8 + 2 * tg + 1]     = p[nt][1];
            psm[warp][g + 8][nt * 8 + 2 * tg]     = p[nt][2];
            psm[warp][g + 8][nt * 8 + 2 * tg + 1] = p[nt][3];
        }
        __syncwarp();
        uint32_t pah[2][4], pal[2][4];
#pragma unroll
        for (int ks = 0; ks < 2; ++ks) {
            hl(psm[warp][g][ks * 8 + tg],         pah[ks][0], pal[ks][0]);
            hl(psm[warp][g + 8][ks * 8 + tg],     pah[ks][1], pal[ks][1]);
            hl(psm[warp][g][ks * 8 + tg + 4],     pah[ks][2], pal[ks][2]);
            hl(psm[warp][g + 8][ks * 8 + tg + 4], pah[ks][3], pal[ks][3]);
        }

#pragma unroll
        for (int nt = 0; nt < 8; ++nt) {
#pragma unroll
            for (int ks = 0; ks < 2; ++ks) {
                uint32_t bh[2], bl[2];
                hl(Vsm[warp][ks * 8 + tg][nt * 8 + g],     bh[0], bl[0]);
                hl(Vsm[warp][ks * 8 + tg + 4][nt * 8 + g], bh[1], bl[1]);
                mma8(c[nt], pah[ks], bh);
                mma8(c[nt], pah[ks], bl);
                mma8(c[nt], pal[ks], bh);
            }
        }
    }

    float sv = sink_scalars[h];
    float fn0 = fmaxf(m0, sv), fn1 = fmaxf(m1, sv);
    float fa0 = __expf(m0 - fn0), fa1 = __expf(m1 - fn1);
    float pk0 = __expf(sv - fn0), pk1 = __expf(sv - fn1);
    float inv0 = 1.f / (l0 * fa0 + pk0);
    float inv1 = 1.f / (l1 * fa1 + pk1);
    const float* vn = v_nulls + h * 64;
#pragma unroll
    for (int nt = 0; nt < 8; ++nt) {
        int col = nt * 8 + 2 * tg;
        float vn0 = vn[col], vn1 = vn[col + 1];
        float* op0 = ctx + (size_t)(qb * 16 + g) * 4096 + h * 64 + col;
        float* op1 = ctx + (size_t)(qb * 16 + g + 8) * 4096 + h * 64 + col;
        *reinterpret_cast<float2*>(op0) =
            make_float2((c[nt][0] * fa0 + pk0 * vn0) * inv0,
                        (c[nt][1] * fa0 + pk0 * vn1) * inv0);
        *reinterpret_cast<float2*>(op1) =
            make_float2((c[nt][2] * fa1 + pk1 * vn0) * inv1,
                        (c[nt][3] * fa1 + pk1 * vn1) * inv1);
    }
}

// ---------------------------------------------------------------------------
__global__ void reduce_out(const float* __restrict__ part, const float* __restrict__ WOb,
                           float* __restrict__ out)
{
    int idx = blockIdx.x * 256 + threadIdx.x;
    int col = idx & 511;
    float b = 0.f;
#pragma unroll
    for (int n = 0; n < 8; ++n) b += WOb[n * 512 + col];
    const int S = T_TOK * 512;
    out[idx] = 0.125f * (part[idx] + part[S + idx] + part[2 * S + idx] + part[3 * S + idx] + b);
}

// ---------------------------------------------------------------------------
extern "C" void kernel_launch(void* const* d_in, const int* in_sizes, int n_in,
                              void* d_out, int out_size)
{
    const float* x   = (const float*)d_in[0];
    const float* WQ  = (const float*)d_in[1];
    const float* WK  = (const float*)d_in[2];
    const float* bK  = (const float*)d_in[3];
    const float* WV  = (const float*)d_in[4];
    const float* bV  = (const float*)d_in[5];
    const float* Am  = (const float*)d_in[6];
    const float* idb = (const float*)d_in[7];
    const float* snk = (const float*)d_in[8];
    const float* vnl = (const float*)d_in[9];
    const float* WO  = (const float*)d_in[10];
    const float* WOb = (const float*)d_in[11];
    float* out = (float*)d_out;

    float *weff, *kraw, *vraw, *Qb, *Kb, *qmb, *kmb, *ctx, *part;
    unsigned long long* mb;
    cudaGetSymbolAddress((void**)&weff, g_Weff);
    cudaGetSymbolAddress((void**)&kraw, g_kraw);
    cudaGetSymbolAddress((void**)&vraw, g_vraw);
    cudaGetSymbolAddress((void**)&Qb,   g_Q);
    cudaGetSymbolAddress((void**)&Kb,   g_K);
    cudaGetSymbolAddress((void**)&qmb,  g_qm);
    cudaGetSymbolAddress((void**)&kmb,  g_km);
    cudaGetSymbolAddress((void**)&ctx,  g_ctx);
    cudaGetSymbolAddress((void**)&part, g_part);
    cudaGetSymbolAddress((void**)&mb,   g_mask);

    // launches 1-3 (ncu -s 5 -c 1 captures launch #4 = qkv_gemm)
    prep_cs<<<128, 256>>>();
    prep_fold<<<dim3(64, 4), 128>>>(Am, idb, WQ, weff, 0);
    prep_fold<<<dim3(64, 4), 128>>>(Am, idb, WQ, weff, 4);

    // launch 4: profiled
    qkv_gemm<<<dim3(40, 8), 256>>>(x, weff, WK, WV, bK, bV, Qb, kraw, vraw);

    km_krope<<<dim3(8, 8), 256>>>(Am, idb, kraw, Kb);

    bmeans_kernel<<<dim3(64, 4), 256>>>(Qb, Kb, qmb, kmb);
    btopk_kernel<<<64, 256>>>(qmb, kmb, mb);

    attn_mma<<<1024, 128>>>(Qb, Kb, vraw, mb, snk, vnl, ctx);

    mma_gemm_nn<4><<<dim3(4, 8, 4), 256>>>(ctx, WO, part, 1024, 512, 4096);
    reduce_out<<<2048, 256>>>(part, WOb, out);
}